// round 15
// baseline (speedup 1.0000x reference)
#include <cuda_runtime.h>

#define Bv 16
#define Cv 512
#define Nv 9216
#define Kv 32
#define TN 512
#define NT (Nv / TN)      // 18 n-tiles for k_assign

#define SL 8              // k_agg n-slices per (b, c-half)
#define NSL (Nv / SL)     // 1152 n per slice
#define CHN 16            // n per staged chunk
#define NCH (NSL / CHN)   // 72 chunks
#define CHC 256           // c per block (c-half)
#define RP 20             // raw fp32 x pitch (words) — aligned cp16 rows
#define TP 12             // bf16x2 tile pitch (words) — conflict-free frag reads

// scratch (no cudaMalloc allowed)
__device__ __align__(16) unsigned g_aw2h[(size_t)Bv * Kv * (Nv / 2)]; // 9.4 MB bf16x2 hi
__device__ __align__(16) unsigned g_aw2l[(size_t)Bv * Kv * (Nv / 2)]; // 9.4 MB bf16x2 lo
__device__ float g_sawp[Bv * NT * Kv];                                // per-tile sums of aw
__device__ __align__(16) float g_part[(size_t)SL * Bv * Kv * Cv];     // 8.4 MB partials

typedef unsigned long long u64;

__device__ __forceinline__ u64 pack2(float lo, float hi) {
    u64 r; asm("mov.b64 %0,{%1,%2};" : "=l"(r) : "f"(lo), "f"(hi)); return r;
}
__device__ __forceinline__ void unpack2(u64 v, float& lo, float& hi) {
    asm("mov.b64 {%0,%1},%2;" : "=f"(lo), "=f"(hi) : "l"(v));
}
__device__ __forceinline__ u64 ffma2(u64 a, u64 b, u64 c) {
    u64 d; asm("fma.rn.f32x2 %0,%1,%2,%3;" : "=l"(d) : "l"(a), "l"(b), "l"(c)); return d;
}
__device__ __forceinline__ unsigned smem_u32(const void* p) {
    unsigned r;
    asm("{ .reg .u64 t; cvta.to.shared.u64 t, %1; cvt.u32.u64 %0, t; }" : "=r"(r) : "l"(p));
    return r;
}
__device__ __forceinline__ void cp16(unsigned dst, const void* src) {
    asm volatile("cp.async.ca.shared.global [%0], [%1], 16;" :: "r"(dst), "l"(src));
}
#define CP_COMMIT() asm volatile("cp.async.commit_group;" ::: "memory")
#define CP_WAIT(N)  asm volatile("cp.async.wait_group %0;" :: "n"(N) : "memory")

// bf16x2 pack: result.lo = bf16(lo), result.hi = bf16(hi)
__device__ __forceinline__ unsigned bf2(float hi, float lo) {
    unsigned u; asm("cvt.rn.bf16x2.f32 %0, %1, %2;" : "=r"(u) : "f"(hi), "f"(lo)); return u;
}
__device__ __forceinline__ float blo(unsigned u) { return __uint_as_float(u << 16); }
__device__ __forceinline__ float bhi(unsigned u) { return __uint_as_float(u & 0xFFFF0000u); }

// m16n8k16 bf16 mma: D += A*B, fp32 accumulate
#define MMA16(d, a0, a1, a2, a3, b0, b1) \
    asm volatile("mma.sync.aligned.m16n8k16.row.col.f32.bf16.bf16.f32 " \
        "{%0,%1,%2,%3}, {%4,%5,%6,%7}, {%8,%9}, {%0,%1,%2,%3};" \
        : "+f"(d[0]), "+f"(d[1]), "+f"(d[2]), "+f"(d[3]) \
        : "r"(a0), "r"(a1), "r"(a2), "r"(a3), "r"(b0), "r"(b1))

// ---------------------------------------------------------------------------
// Kernel 1: logits via scaled L2 (fp32 FFMA2), softmax K=32, write aw as
// bf16x2 hi/lo in the mma A-fragment layout [b][k][n/2], plus deterministic
// per-tile sum_aw partials. Thread owns n = n0+2t (low half) and n0+2t+1.
// ---------------------------------------------------------------------------
__global__ void __launch_bounds__(256, 2) k_assign(
    const float* __restrict__ x, const float* __restrict__ cw,
    const float* __restrict__ scale)
{
    extern __shared__ float cwT[];                 // [Cv][Kv] = 64 KB
    __shared__ float s_scale[Kv], s_sc2[Kv];
    const int tid = threadIdx.x;
    const int b   = blockIdx.y;
    const int n0  = blockIdx.x * TN;

    for (int i = tid; i < Cv * Kv; i += 256) {
        int k = i & 31, c = i >> 5;
        cwT[c * Kv + k] = cw[k * Cv + c];
    }
    __syncthreads();
    if (tid < Kv) {
        float s2 = 0.0f;
        #pragma unroll 8
        for (int c = 0; c < Cv; c++) { float v = cwT[c * Kv + tid]; s2 = fmaf(v, v, s2); }
        float sk = scale[tid];
        s_scale[tid] = sk;
        s_sc2[tid]   = sk * s2;
    }
    __syncthreads();

    const float* xb = x + (size_t)b * Cv * Nv + n0 + 2 * tid;

    u64 acc0[16], acc1[16];
    #pragma unroll
    for (int p = 0; p < 16; p++) { acc0[p] = 0ull; acc1[p] = 0ull; }
    u64 x2p = 0ull;

    float2 buf[8];
    #pragma unroll
    for (int i = 0; i < 8; i++) buf[i] = *reinterpret_cast<const float2*>(xb + (size_t)i * Nv);

    for (int c0 = 0; c0 < Cv; c0 += 8) {
        #pragma unroll
        for (int i = 0; i < 8; i++) {
            float2 xv = buf[i];
            int cn = c0 + 8 + i; cn = (cn < Cv) ? cn : 0;
            buf[i] = *reinterpret_cast<const float2*>(xb + (size_t)cn * Nv);

            u64 xp = pack2(xv.x, xv.y);
            x2p = ffma2(xp, xp, x2p);
            u64 d0 = pack2(xv.x, xv.x);
            u64 d1 = pack2(xv.y, xv.y);
            const ulonglong2* row = reinterpret_cast<const ulonglong2*>(cwT + (c0 + i) * Kv);
            #pragma unroll
            for (int q = 0; q < 8; q++) {
                ulonglong2 w = row[q];
                acc0[2 * q]     = ffma2(d0, w.x, acc0[2 * q]);
                acc1[2 * q]     = ffma2(d1, w.x, acc1[2 * q]);
                acc0[2 * q + 1] = ffma2(d0, w.y, acc0[2 * q + 1]);
                acc1[2 * q + 1] = ffma2(d1, w.y, acc1[2 * q + 1]);
            }
        }
    }

    float xcA[Kv], xcB[Kv], x2A, x2B;
    #pragma unroll
    for (int p = 0; p < 16; p++) {
        unpack2(acc0[p], xcA[2 * p], xcA[2 * p + 1]);
        unpack2(acc1[p], xcB[2 * p], xcB[2 * p + 1]);
    }
    unpack2(x2p, x2A, x2B);

    // softmax (in place) for both owned n's
    {
        float m = -1e30f;
        #pragma unroll
        for (int k = 0; k < Kv; k++) {
            float v = fmaf(s_scale[k], x2A - 2.0f * xcA[k], s_sc2[k]);
            xcA[k] = v; m = fmaxf(m, v);
        }
        float s = 0.0f;
        #pragma unroll
        for (int k = 0; k < Kv; k++) { float e = __expf(xcA[k] - m); xcA[k] = e; s += e; }
        float r = 1.0f / s;
        #pragma unroll
        for (int k = 0; k < Kv; k++) xcA[k] *= r;
    }
    {
        float m = -1e30f;
        #pragma unroll
        for (int k = 0; k < Kv; k++) {
            float v = fmaf(s_scale[k], x2B - 2.0f * xcB[k], s_sc2[k]);
            xcB[k] = v; m = fmaxf(m, v);
        }
        float s = 0.0f;
        #pragma unroll
        for (int k = 0; k < Kv; k++) { float e = __expf(xcB[k] - m); xcB[k] = e; s += e; }
        float r = 1.0f / s;
        #pragma unroll
        for (int k = 0; k < Kv; k++) xcB[k] *= r;
    }

    // write aw as bf16x2 hi/lo, layout [b][k][n/2] (pair = (n even, n odd))
    {
        const size_t base = (size_t)b * Kv * (Nv / 2) + (n0 >> 1) + tid;
        #pragma unroll
        for (int k = 0; k < Kv; k++) {
            unsigned h = bf2(xcB[k], xcA[k]);          // lo half = even n
            float rA = xcA[k] - blo(h);
            float rB = xcB[k] - bhi(h);
            unsigned lo = bf2(rB, rA);
            g_aw2h[base + (size_t)k * (Nv / 2)] = h;
            g_aw2l[base + (size_t)k * (Nv / 2)] = lo;
        }
    }

    // deterministic block-level sum_aw (fp32): transpose through smem
    __syncthreads();
    float* red = cwT;                              // [256][33]
    #pragma unroll
    for (int k = 0; k < Kv; k++) red[tid * 33 + k] = xcA[k] + xcB[k];
    __syncthreads();
    if (tid < Kv) {
        float s = 0.0f;
        #pragma unroll 8
        for (int t = 0; t < 256; t++) s += red[t * 33 + tid];
        g_sawp[(b * NT + blockIdx.x) * Kv + tid] = s;
    }
}

// ---------------------------------------------------------------------------
// Kernel 2 (bf16 split tensor cores): partial[k][c] = sum_n aw[n][k]*x[c][n]
// for one (b, c-half 256, n-slice 1152) via mma m16n8k16 bf16, 3 MMAs
// (ah*bh + al*bh + ah*bl), fp32 acc. All conversions OUT of the inner loop:
//   aw tiles cp.async'd pre-split from k_assign (A-frag layout, zero work)
//   x converted once per chunk in an own-row staging pass (raw fp32 -> bf16x2)
// Inner loop per thread-chunk: 40 LDS.32 + 24 MMA, zero cvt/pack.
// Block: 256 thr / 8 warps = (k-half mh) x (c-quad cq, 64 c). 70 KB smem,
// 2 CTAs/SM, grid (2 ch x 8 sl) x 16 b = 256 blocks.
// ---------------------------------------------------------------------------
__global__ void __launch_bounds__(256, 2) k_agg(
    const float* __restrict__ x, float* __restrict__ part)
{
    extern __shared__ float sm[];
    float*    raw = sm;                                  // [2][256][RP] fp32
    unsigned* xh  = (unsigned*)(sm + 2 * 256 * RP);      // [256][TP] bf16x2 hi
    unsigned* xl  = xh + 256 * TP;                       // [256][TP] bf16x2 lo
    unsigned* awh = xl + 256 * TP;                       // [2][32][TP]
    unsigned* awl = awh + 2 * 32 * TP;                   // [2][32][TP]
    const unsigned raw_u = smem_u32(raw);
    const unsigned awh_u = smem_u32(awh);
    const unsigned awl_u = smem_u32(awl);

    const int tid = threadIdx.x, w = tid >> 5, l = tid & 31;
    const int gid = l >> 2, tig = l & 3;
    const int b  = blockIdx.y;
    const int ch = blockIdx.x >> 3;
    const int sl = blockIdx.x & 7;
    const int mh = w & 1;                  // k-half
    const int cq = w >> 1;                 // c-quad (64 c)
    const int nst = sl * NSL;
    const int c0g = ch * CHC;

    const float* xb = x + (size_t)b * Cv * Nv + (size_t)(c0g + tid) * Nv + nst;
    const unsigned* ahs = g_aw2h + (size_t)b * Kv * (Nv / 2) + (nst >> 1);
    const unsigned* als = g_aw2l + (size_t)b * Kv * (Nv / 2) + (nst >> 1);

    float acc[8][4];
    #pragma unroll
    for (int ct = 0; ct < 8; ct++)
        #pragma unroll
        for (int i = 0; i < 4; i++) acc[ct][i] = 0.0f;

    // aw staging descriptor: threads 0..127 stage (hi|lo) x (k, half-row)
    const int awk = (tid & 63) >> 1, awhf = tid & 1;
    const unsigned awdst = ((tid < 64) ? awh_u : awl_u)
                         + (unsigned)(awk * TP + awhf * 4) * 4;
    const unsigned* awsrc = (tid < 64) ? ahs : als;

    // ---- stage chunk 0 ----
    #pragma unroll
    for (int j = 0; j < 4; j++)
        cp16(raw_u + (unsigned)(tid * RP + 4 * j) * 4, xb + 4 * j);
    if (tid < 128)
        cp16(awdst, awsrc + (size_t)awk * (Nv / 2) + awhf * 4);
    CP_COMMIT();

    for (int t = 0; t < NCH; t++) {
        __syncthreads();                   // compute t-1 done: tiles + aw buf free
        if (t + 1 < NCH) {
            const int sb = (t + 1) & 1;
            const int n0 = (t + 1) * CHN;
            #pragma unroll
            for (int j = 0; j < 4; j++)
                cp16(raw_u + (unsigned)(sb * 256 * RP + tid * RP + 4 * j) * 4,
                     xb + n0 + 4 * j);
            if (tid < 128)
                cp16(awdst + (unsigned)(sb * 32 * TP) * 4,
                     awsrc + (size_t)awk * (Nv / 2) + (t + 1) * (CHN / 2) + awhf * 4);
            CP_COMMIT();
            CP_WAIT(1);                    // chunk t landed (t+1 in flight)
        } else {
            CP_WAIT(0);
        }

        // convert own raw row t -> bf16x2 tiles (each thread reads only what
        // it cp'd itself: no barrier needed before this)
        {
            const float* rr = raw + (t & 1) * 256 * RP + tid * RP;
            unsigned hrow[8], lrow[8];
            #pragma unroll
            for (int j = 0; j < 4; j++) {
                float4 v = reinterpret_cast<const float4*>(rr)[j];
                unsigned h0 = bf2(v.y, v.x);
                unsigned h1 = bf2(v.w, v.z);
                float r0 = v.x - blo(h0), r1 = v.y - bhi(h0);
                float r2 = v.z - blo(h1), r3 = v.w - bhi(h1);
                hrow[2 * j] = h0; hrow[2 * j + 1] = h1;
                lrow[2 * j] = bf2(r1, r0); lrow[2 * j + 1] = bf2(r3, r2);
            }
            uint4* hd = reinterpret_cast<uint4*>(xh + tid * TP);
            uint4* ld = reinterpret_cast<uint4*>(xl + tid * TP);
            hd[0] = make_uint4(hrow[0], hrow[1], hrow[2], hrow[3]);
            hd[1] = make_uint4(hrow[4], hrow[5], hrow[6], hrow[7]);
            ld[0] = make_uint4(lrow[0], lrow[1], lrow[2], lrow[3]);
            ld[1] = make_uint4(lrow[4], lrow[5], lrow[6], lrow[7]);
        }
        __syncthreads();                   // tiles + aw chunk t visible to all

        // compute chunk t: A frags (pre-split), B frags, 3 MMA passes
        const unsigned* aht = awh + (t & 1) * 32 * TP + (mh * 16 + gid) * TP;
        const unsigned* alt = awl + (t & 1) * 32 * TP + (mh * 16 + gid) * TP;
        unsigned Ah0 = aht[tig],          Ah1 = aht[8 * TP + tig];
        unsigned Ah2 = aht[tig + 4],      Ah3 = aht[8 * TP + tig + 4];
        unsigned Al0 = alt[tig],          Al1 = alt[8 * TP + tig];
        unsigned Al2 = alt[tig + 4],      Al3 = alt[8 * TP + tig + 4];

        unsigned bh0[8], bh1[8], bl0[8], bl1[8];
        #pragma unroll
        for (int ct = 0; ct < 8; ct++) {
            int cc = cq * 64 + ct * 8 + gid;
            bh0[ct] = xh[cc * TP + tig];
            bh1[ct] = xh[cc * TP + tig + 4];
            bl0[ct] = xl[cc * TP + tig];
            bl1[ct] = xl[cc * TP + tig + 4];
        }
        #pragma unroll
        for (int ct = 0; ct < 8; ct++)
            MMA16(acc[ct], Ah0, Ah1, Ah2, Ah3, bh0[ct], bh1[ct]);
        #pragma unroll
        for (int ct = 0; ct < 8; ct++)
            MMA16(acc[ct], Al0, Al1, Al2, Al3, bh0[ct], bh1[ct]);
        #pragma unroll
        for (int ct = 0; ct < 8; ct++)
            MMA16(acc[ct], Ah0, Ah1, Ah2, Ah3, bl0[ct], bl1[ct]);
    }

    // epilogue: warp writes its 16k x 64c partial tile
    float* pr0 = part + (((size_t)sl * Bv + b) * Kv + mh * 16 + gid) * Cv
                      + c0g + cq * 64;
    #pragma unroll
    for (int ct = 0; ct < 8; ct++) {
        int cc = ct * 8 + tig * 2;
        *reinterpret_cast<float2*>(pr0 + cc)            = make_float2(acc[ct][0], acc[ct][1]);
        *reinterpret_cast<float2*>(pr0 + 8 * Cv + cc)   = make_float2(acc[ct][2], acc[ct][3]);
    }
}

// ---------------------------------------------------------------------------
// Kernel 3: out[b][k][c] = sum_s part[s][b][k][c] - sum_aw[b][k] * cw[k][c]
// ---------------------------------------------------------------------------
__global__ void __launch_bounds__(256) k_fin(
    const float* __restrict__ cw, float* __restrict__ out)
{
    __shared__ float ssum;
    const int bx = blockIdx.x;             // 0..511
    const int b = bx >> 5, k = bx & 31;
    const int tid = threadIdx.x;

    if (tid == 0) {
        float s = 0.0f;
        #pragma unroll
        for (int t = 0; t < NT; t++) s += g_sawp[(b * NT + t) * Kv + k];
        ssum = s;
    }
    __syncthreads();

    float2 v = make_float2(0.0f, 0.0f);
    #pragma unroll
    for (int s = 0; s < SL; s++) {
        float2 p = reinterpret_cast<const float2*>(
            g_part + (((size_t)s * Bv + b) * Kv + k) * Cv)[tid];
        v.x += p.x; v.y += p.y;
    }
    float2 cwv = reinterpret_cast<const float2*>(cw + (size_t)k * Cv)[tid];
    float sv = ssum;
    float2 o;
    o.x = v.x - sv * cwv.x;
    o.y = v.y - sv * cwv.y;
    reinterpret_cast<float2*>(out + ((size_t)b * Kv + k) * Cv)[tid] = o;
}

extern "C" void kernel_launch(void* const* d_in, const int* in_sizes, int n_in,
                              void* d_out, int out_size)
{
    const float* x  = (const float*)d_in[0];   // (B, C, H, W)
    const float* cw = (const float*)d_in[1];   // (K, C)
    const float* sc = (const float*)d_in[2];   // (K,)
    float* out = (float*)d_out;                // (B, K, C)

    const int agg_smem = (2 * 256 * RP + 2 * 256 * TP + 4 * 32 * TP) * 4;  // 71680 B

    static int inited = 0;
    if (!inited) {
        cudaFuncSetAttribute(k_assign, cudaFuncAttributeMaxDynamicSharedMemorySize, Cv * Kv * 4);
        cudaFuncSetAttribute(k_agg, cudaFuncAttributeMaxDynamicSharedMemorySize, agg_smem);
        inited = 1;
    }

    float* part;
    cudaGetSymbolAddress((void**)&part, g_part);   // no alloc; capture-safe

    k_assign<<<dim3(NT, Bv), 256, Cv * Kv * 4>>>(x, cw, sc);
    k_agg<<<dim3(16, Bv), 256, agg_smem>>>(x, part);
    k_fin<<<Bv * Kv, 256>>>(cw, out);
}